// round 1
// baseline (speedup 1.0000x reference)
#include <cuda_runtime.h>
#include <math.h>

// ---------------- problem constants ----------------
#define NTOK 2048      // B*S
#define D    1024
#define H    4096
#define HE   4096
#define E    8
#define TOPK 2
#define LN_EPS 1e-5f

// ---------------- scratch (device globals; no allocation allowed) ----------
__device__ float g_h    [NTOK * D];        // x + pos
__device__ float g_xhat [NTOK * D];        // shared LN stats, no affine
__device__ float g_r    [NTOK * D];        // router LN out
__device__ float g_rh   [NTOK * H];        // router hidden
__device__ int   g_counts[E];
__device__ int   g_base  [E];
__device__ int   g_perm  [E * NTOK];
__device__ float g_gatew [E * NTOK];
__device__ float g_y    [NTOK * TOPK * D]; // gathered expert inputs (4096 rows)
__device__ float g_f1   [NTOK * TOPK * HE];
__device__ float g_f2   [NTOK * TOPK * D];
__device__ float g_comb [NTOK * D];
__device__ float g_cln  [NTOK * D];
__device__ float g_ch   [NTOK * 2 * D];
__device__ float g_co   [NTOK * D];

// ---------------- helpers ----------------
__device__ __forceinline__ float gelu_f(float x) {
    return 0.5f * x * (1.0f + erff(x * 0.7071067811865475f));
}

__device__ __forceinline__ float block_reduce_sum256(float v, float* sh) {
    int tid = threadIdx.x;
    sh[tid] = v;
    __syncthreads();
#pragma unroll
    for (int s = 128; s > 0; s >>= 1) {
        if (tid < s) sh[tid] += sh[tid + s];
        __syncthreads();
    }
    float r = sh[0];
    __syncthreads();
    return r;
}

// ---------------- kernels ----------------

__global__ void zero_kernel(float* comb, int n, int* counts) {
    int i = blockIdx.x * blockDim.x + threadIdx.x;
    if (i < n) comb[i] = 0.f;
    if (i < E) counts[i] = 0;
}

// h = x + positional encoding
__global__ void posadd_kernel(const float* __restrict__ x, float* __restrict__ h) {
    int t = blockIdx.x;          // 0..NTOK-1
    int s = t & 1023;            // sequence position
    const float LOG1E4 = 9.210340371976184f; // ln(10000)
    for (int d = threadIdx.x; d < D; d += 256) {
        int j2 = d & ~1;         // even index 2*floor(d/2)
        float div = expf(-LOG1E4 * (float)j2 * (1.0f / (float)D));
        float a = (float)s * div;
        float pe = (d & 1) ? cosf(a) : sinf(a);
        h[(size_t)t * D + d] = x[(size_t)t * D + d] + pe;
    }
}

// LN over h producing xhat (no affine) and r = xhat*g+b (router input)
__global__ void ln_dual_kernel(const float* __restrict__ hbuf,
                               const float* __restrict__ g, const float* __restrict__ b,
                               float* __restrict__ xhat, float* __restrict__ r) {
    __shared__ float sh[256];
    int t = blockIdx.x, tid = threadIdx.x;
    const float* row = hbuf + (size_t)t * D;
    float v[4];
    float s = 0.f;
#pragma unroll
    for (int i = 0; i < 4; i++) { v[i] = row[tid + 256 * i]; s += v[i]; }
    s = block_reduce_sum256(s, sh);
    float mean = s * (1.f / (float)D);
    float q = 0.f;
#pragma unroll
    for (int i = 0; i < 4; i++) { float dd = v[i] - mean; q += dd * dd; }
    q = block_reduce_sum256(q, sh);
    float rstd = rsqrtf(q * (1.f / (float)D) + LN_EPS);
#pragma unroll
    for (int i = 0; i < 4; i++) {
        int d = tid + 256 * i;
        float xh = (v[i] - mean) * rstd;
        xhat[(size_t)t * D + d] = xh;
        r[(size_t)t * D + d] = xh * g[d] + b[d];
    }
}

// out = LN(X [+ X2]) * g + b   (X2 may be null)
__global__ void ln_affine_kernel(const float* __restrict__ X, const float* __restrict__ X2,
                                 const float* __restrict__ g, const float* __restrict__ b,
                                 float* __restrict__ out) {
    __shared__ float sh[256];
    int t = blockIdx.x, tid = threadIdx.x;
    float v[4];
    float s = 0.f;
#pragma unroll
    for (int i = 0; i < 4; i++) {
        int d = tid + 256 * i;
        float val = X[(size_t)t * D + d];
        if (X2) val += X2[(size_t)t * D + d];
        v[i] = val; s += val;
    }
    s = block_reduce_sum256(s, sh);
    float mean = s * (1.f / (float)D);
    float q = 0.f;
#pragma unroll
    for (int i = 0; i < 4; i++) { float dd = v[i] - mean; q += dd * dd; }
    q = block_reduce_sum256(q, sh);
    float rstd = rsqrtf(q * (1.f / (float)D) + LN_EPS);
#pragma unroll
    for (int i = 0; i < 4; i++) {
        int d = tid + 256 * i;
        out[(size_t)t * D + d] = (v[i] - mean) * rstd * g[d] + b[d];
    }
}

// ---------------- SGEMM: C[M,N] = act(A[M,K] @ B[K,N] + bias[N]) -----------
// BM=BN=128, BK=8, 256 threads, 8x8 per thread (split 64-apart for bank-free LDS)
#define BM 128
#define BN 128
#define BK 8

template <bool DOGELU>
__device__ __forceinline__ void gemm_body(const float* __restrict__ A,
                                          const float* __restrict__ B,
                                          const float* __restrict__ bias,
                                          float* __restrict__ C,
                                          int M, int N, int K, int m0, int n0) {
    __shared__ float As[BK][BM];
    __shared__ float Bs[BK][BN];
    int tid = threadIdx.x;
    int tx = tid & 15, ty = tid >> 4;

    float acc[8][8];
#pragma unroll
    for (int i = 0; i < 8; i++)
#pragma unroll
        for (int j = 0; j < 8; j++) acc[i][j] = 0.f;

    int arow = tid >> 1;          // 0..127
    int acol = (tid & 1) * 4;     // 0 or 4
    int brow = tid >> 5;          // 0..7
    int bcol = (tid & 31) * 4;    // 0..124

    const float* Aptr = A + (size_t)(m0 + arow) * K + acol;
    const float* Bptr = B + (size_t)brow * N + n0 + bcol;
    bool aval = (m0 + arow) < M;

    for (int k0 = 0; k0 < K; k0 += BK) {
        float4 av = aval ? *(const float4*)Aptr : make_float4(0.f, 0.f, 0.f, 0.f);
        float4 bv = *(const float4*)Bptr;
        As[acol + 0][arow] = av.x;
        As[acol + 1][arow] = av.y;
        As[acol + 2][arow] = av.z;
        As[acol + 3][arow] = av.w;
        *(float4*)&Bs[brow][bcol] = bv;
        __syncthreads();
#pragma unroll
        for (int k = 0; k < BK; k++) {
            float4 a0 = *(const float4*)&As[k][ty * 4];
            float4 a1 = *(const float4*)&As[k][ty * 4 + 64];
            float4 b0 = *(const float4*)&Bs[k][tx * 4];
            float4 b1 = *(const float4*)&Bs[k][tx * 4 + 64];
            float ar[8] = {a0.x, a0.y, a0.z, a0.w, a1.x, a1.y, a1.z, a1.w};
            float br[8] = {b0.x, b0.y, b0.z, b0.w, b1.x, b1.y, b1.z, b1.w};
#pragma unroll
            for (int i = 0; i < 8; i++)
#pragma unroll
                for (int j = 0; j < 8; j++) acc[i][j] += ar[i] * br[j];
        }
        __syncthreads();
        Aptr += BK;
        Bptr += (size_t)BK * N;
    }

#pragma unroll
    for (int i = 0; i < 8; i++) {
        int r = m0 + ty * 4 + ((i < 4) ? i : (64 + i - 4));
        if (r >= M) continue;
#pragma unroll
        for (int j = 0; j < 8; j++) {
            int c = n0 + tx * 4 + ((j < 4) ? j : (64 + j - 4));
            float v = acc[i][j] + bias[c];
            if (DOGELU) v = gelu_f(v);
            C[(size_t)r * N + c] = v;
        }
    }
}

template <bool DOGELU>
__global__ void __launch_bounds__(256)
gemm_kernel(const float* __restrict__ A, const float* __restrict__ B,
            const float* __restrict__ bias, float* __restrict__ C,
            int M, int N, int K) {
    int m0 = blockIdx.y * BM;
    int n0 = blockIdx.x * BN;
    if (m0 >= M) return;
    gemm_body<DOGELU>(A, B, bias, C, M, N, K, m0, n0);
}

// grouped expert GEMM: per-expert A rows at base[e], weights B[e], bias[e]
template <bool DOGELU>
__global__ void __launch_bounds__(256)
gemm_expert_kernel(const float* __restrict__ Abase, const float* __restrict__ Ball,
                   const float* __restrict__ biasall, float* __restrict__ Cbase,
                   const int* __restrict__ counts, const int* __restrict__ bases,
                   int N, int K) {
    int e = blockIdx.z;
    int M = counts[e];
    int m0 = blockIdx.y * BM;
    int n0 = blockIdx.x * BN;
    if (m0 >= M) return;
    const float* A = Abase + (size_t)bases[e] * K;
    const float* B = Ball + (size_t)e * K * N;
    const float* bias = biasall + (size_t)e * N;
    float* C = Cbase + (size_t)bases[e] * N;
    gemm_body<DOGELU>(A, B, bias, C, M, N, K, m0, n0);
}

// ---------------- router: logits -> softmax(T) -> top2 -> compact ----------
__global__ void router_kernel(const float* __restrict__ rh, const float* __restrict__ w2,
                              const float* __restrict__ b2, const float* __restrict__ temp,
                              int* __restrict__ counts, int* __restrict__ perm,
                              float* __restrict__ gatew) {
    __shared__ float sh[E * 256];
    int t = blockIdx.x, tid = threadIdx.x;
    float acc[E];
#pragma unroll
    for (int e = 0; e < E; e++) acc[e] = 0.f;
    const float* row = rh + (size_t)t * H;
    for (int k = tid; k < H; k += 256) {
        float v = row[k];
        const float4* w = (const float4*)(w2 + (size_t)k * E);
        float4 w0 = w[0], w1 = w[1];
        acc[0] += v * w0.x; acc[1] += v * w0.y; acc[2] += v * w0.z; acc[3] += v * w0.w;
        acc[4] += v * w1.x; acc[5] += v * w1.y; acc[6] += v * w1.z; acc[7] += v * w1.w;
    }
#pragma unroll
    for (int e = 0; e < E; e++) sh[e * 256 + tid] = acc[e];
    __syncthreads();
#pragma unroll
    for (int s = 128; s > 0; s >>= 1) {
        if (tid < s)
#pragma unroll
            for (int e = 0; e < E; e++) sh[e * 256 + tid] += sh[e * 256 + tid + s];
        __syncthreads();
    }
    if (tid == 0) {
        float invt = 1.0f / temp[0];
        float l[E];
        float mx = -1e30f;
#pragma unroll
        for (int e = 0; e < E; e++) { l[e] = (sh[e * 256] + b2[e]) * invt; mx = fmaxf(mx, l[e]); }
        float se = 0.f;
        float p[E];
#pragma unroll
        for (int e = 0; e < E; e++) { p[e] = expf(l[e] - mx); se += p[e]; }
        float inv = 1.0f / se;
#pragma unroll
        for (int e = 0; e < E; e++) p[e] *= inv;
        int i1 = 0;
#pragma unroll
        for (int e = 1; e < E; e++) if (p[e] > p[i1]) i1 = e;
        int i2 = (i1 == 0) ? 1 : 0;
#pragma unroll
        for (int e = 0; e < E; e++) if (e != i1 && p[e] > p[i2]) i2 = e;
        int pos1 = atomicAdd(&counts[i1], 1);
        perm[i1 * NTOK + pos1] = t;
        gatew[i1 * NTOK + pos1] = p[i1];
        int pos2 = atomicAdd(&counts[i2], 1);
        perm[i2 * NTOK + pos2] = t;
        gatew[i2 * NTOK + pos2] = p[i2];
    }
}

__global__ void base_kernel(const int* __restrict__ counts, int* __restrict__ bases) {
    int s = 0;
    for (int e = 0; e < E; e++) { bases[e] = s; s += counts[e]; }
}

// gather: y[base[e]+i] = xhat[perm] * e_ln_g[e] + e_ln_b[e]
__global__ void gather_kernel(const float* __restrict__ xhat, const float* __restrict__ elng,
                              const float* __restrict__ elnb, const int* __restrict__ counts,
                              const int* __restrict__ bases, const int* __restrict__ perm,
                              float* __restrict__ y) {
    int e = blockIdx.y, i = blockIdx.x;
    if (i >= counts[e]) return;
    int t = perm[e * NTOK + i];
    const float* src = xhat + (size_t)t * D;
    const float* g = elng + (size_t)e * D;
    const float* b = elnb + (size_t)e * D;
    float* dst = y + (size_t)(bases[e] + i) * D;
    for (int d = threadIdx.x; d < D; d += 256)
        dst[d] = src[d] * g[d] + b[d];
}

// scatter: combined[t] += gate * f2_row   (exactly 2 adds per row -> deterministic)
__global__ void scatter_kernel(const float* __restrict__ f2, const int* __restrict__ counts,
                               const int* __restrict__ bases, const int* __restrict__ perm,
                               const float* __restrict__ gatew, float* __restrict__ comb) {
    int e = blockIdx.y, i = blockIdx.x;
    if (i >= counts[e]) return;
    int t = perm[e * NTOK + i];
    float gw = gatew[e * NTOK + i];
    const float* src = f2 + (size_t)(bases[e] + i) * D;
    float* dst = comb + (size_t)t * D;
    for (int d = threadIdx.x; d < D; d += 256)
        atomicAdd(&dst[d], gw * src[d]);
}

// ---------------- launch ----------------
extern "C" void kernel_launch(void* const* d_in, const int* in_sizes, int n_in,
                              void* d_out, int out_size) {
    const float* x      = (const float*)d_in[0];
    const float* r_ln_g = (const float*)d_in[1];
    const float* r_ln_b = (const float*)d_in[2];
    const float* r_w1   = (const float*)d_in[3];
    const float* r_b1   = (const float*)d_in[4];
    const float* r_w2   = (const float*)d_in[5];
    const float* r_b2   = (const float*)d_in[6];
    const float* temp   = (const float*)d_in[7];
    const float* e_ln_g = (const float*)d_in[8];
    const float* e_ln_b = (const float*)d_in[9];
    const float* e_w1   = (const float*)d_in[10];
    const float* e_b1   = (const float*)d_in[11];
    const float* e_w2   = (const float*)d_in[12];
    const float* e_b2   = (const float*)d_in[13];
    const float* c_ln_g = (const float*)d_in[14];
    const float* c_ln_b = (const float*)d_in[15];
    const float* c_w1   = (const float*)d_in[16];
    const float* c_b1   = (const float*)d_in[17];
    const float* c_w2   = (const float*)d_in[18];
    const float* c_b2   = (const float*)d_in[19];
    const float* o_ln_g = (const float*)d_in[20];
    const float* o_ln_b = (const float*)d_in[21];
    float* out = (float*)d_out;

    // resolve device-global scratch addresses (host side; cheap, capture-safe)
    float *p_h, *p_xhat, *p_r, *p_rh, *p_gatew, *p_y, *p_f1, *p_f2, *p_comb, *p_cln, *p_ch, *p_co;
    int *p_counts, *p_base, *p_perm;
    cudaGetSymbolAddress((void**)&p_h, g_h);
    cudaGetSymbolAddress((void**)&p_xhat, g_xhat);
    cudaGetSymbolAddress((void**)&p_r, g_r);
    cudaGetSymbolAddress((void**)&p_rh, g_rh);
    cudaGetSymbolAddress((void**)&p_counts, g_counts);
    cudaGetSymbolAddress((void**)&p_base, g_base);
    cudaGetSymbolAddress((void**)&p_perm, g_perm);
    cudaGetSymbolAddress((void**)&p_gatew, g_gatew);
    cudaGetSymbolAddress((void**)&p_y, g_y);
    cudaGetSymbolAddress((void**)&p_f1, g_f1);
    cudaGetSymbolAddress((void**)&p_f2, g_f2);
    cudaGetSymbolAddress((void**)&p_comb, g_comb);
    cudaGetSymbolAddress((void**)&p_cln, g_cln);
    cudaGetSymbolAddress((void**)&p_ch, g_ch);
    cudaGetSymbolAddress((void**)&p_co, g_co);

    // 0. zero combined + counts
    zero_kernel<<<(NTOK * D + 255) / 256, 256>>>(p_comb, NTOK * D, p_counts);
    // 1. h = x + pos
    posadd_kernel<<<NTOK, 256>>>(x, p_h);
    // 2. shared LN stats -> xhat, router input r
    ln_dual_kernel<<<NTOK, 256>>>(p_h, r_ln_g, r_ln_b, p_xhat, p_r);
    // 3. router hidden: rh = gelu(r @ r_w1 + r_b1)   [2048,4096]
    gemm_kernel<true><<<dim3(H / BN, NTOK / BM), 256>>>(p_r, r_w1, r_b1, p_rh, NTOK, H, D);
    // 4. logits -> softmax -> top2 -> compaction
    router_kernel<<<NTOK, 256>>>(p_rh, r_w2, r_b2, temp, p_counts, p_perm, p_gatew);
    // 5. prefix sum of counts
    base_kernel<<<1, 1>>>(p_counts, p_base);
    // 6. gather expert inputs with per-expert LN affine
    gather_kernel<<<dim3(NTOK, E), 256>>>(p_xhat, e_ln_g, e_ln_b, p_counts, p_base, p_perm, p_y);
    // 7. expert FFN layer 1: f1 = gelu(y @ e_w1[e] + e_b1[e])   [4096 rows, HE]
    gemm_expert_kernel<true><<<dim3(HE / BN, NTOK / BM, E), 256>>>(
        p_y, e_w1, e_b1, p_f1, p_counts, p_base, HE, D);
    // 8. expert FFN layer 2: f2 = f1 @ e_w2[e] + e_b2[e]        [4096 rows, D]
    gemm_expert_kernel<false><<<dim3(D / BN, NTOK / BM, E), 256>>>(
        p_f1, e_w2, e_b2, p_f2, p_counts, p_base, D, HE);
    // 9. scatter-combine with gates
    scatter_kernel<<<dim3(NTOK, E), 256>>>(p_f2, p_counts, p_base, p_perm, p_gatew, p_comb);
    // 10. combiner LN
    ln_affine_kernel<<<NTOK, 256>>>(p_comb, nullptr, c_ln_g, c_ln_b, p_cln);
    // 11. combiner MLP
    gemm_kernel<true><<<dim3(2 * D / BN, NTOK / BM), 256>>>(p_cln, c_w1, c_b1, p_ch, NTOK, 2 * D, D);
    gemm_kernel<false><<<dim3(D / BN, NTOK / BM), 256>>>(p_ch, c_w2, c_b2, p_co, NTOK, D, 2 * D);
    // 12. out = LN(h + co) * o_g + o_b
    ln_affine_kernel<<<NTOK, 256>>>(p_h, p_co, o_ln_g, o_ln_b, out);
}

// round 3
// speedup vs baseline: 3.2033x; 3.2033x over previous
#include <cuda_runtime.h>
#include <cstdint>
#include <math.h>

// ---------------- problem constants ----------------
#define NTOK 2048      // B*S
#define D    1024
#define H    4096
#define HE   4096
#define E    8
#define LN_EPS 1e-5f

// ---------------- scratch (device globals) ----------------
__device__ float g_h    [NTOK * D];
__device__ float g_xhat [NTOK * D];
__device__ float g_r    [NTOK * D];
__device__ float g_rh   [NTOK * H];
__device__ int   g_counts[E];
__device__ int   g_base  [E];
__device__ int   g_perm  [E * NTOK];
__device__ float g_gatew [E * NTOK];
__device__ float g_y    [2 * NTOK * D];
__device__ float g_f1   [2 * NTOK * HE];
__device__ float g_f2   [2 * NTOK * D];
__device__ float g_comb [NTOK * D];
__device__ float g_cln  [NTOK * D];
__device__ float g_ch   [NTOK * 2 * D];
__device__ float g_co   [NTOK * D];

// ---------------- helpers ----------------
__device__ __forceinline__ float gelu_f(float x) {
    return 0.5f * x * (1.0f + erff(x * 0.7071067811865475f));
}
__device__ __forceinline__ float to_tf32(float x) {
    uint32_t u;
    asm("cvt.rna.tf32.f32 %0, %1;" : "=r"(u) : "f"(x));
    return __uint_as_float(u);
}
__device__ __forceinline__ uint32_t smem_u32(const void* p) {
    uint32_t a;
    asm("{ .reg .u64 t; cvta.to.shared.u64 t, %1; cvt.u32.u64 %0, t; }" : "=r"(a) : "l"(p));
    return a;
}
__device__ __forceinline__ float block_reduce_sum256(float v, float* sh) {
    int tid = threadIdx.x;
    sh[tid] = v;
    __syncthreads();
#pragma unroll
    for (int s = 128; s > 0; s >>= 1) {
        if (tid < s) sh[tid] += sh[tid + s];
        __syncthreads();
    }
    float r = sh[0];
    __syncthreads();
    return r;
}

// cp.async (baseline PTX, compute_80+)
#define CP_ASYNC_CG(dst, src, srcsz) \
    asm volatile("cp.async.cg.shared.global [%0], [%1], 16, %2;" \
        :: "r"(dst), "l"(src), "r"(srcsz) : "memory")
#define CP_COMMIT() asm volatile("cp.async.commit_group;" ::: "memory")
#define CP_WAIT1()  asm volatile("cp.async.wait_group 1;" ::: "memory")

__device__ __forceinline__ void mma_tf32(float* c, const uint32_t* a, const uint32_t* b) {
    asm volatile(
        "mma.sync.aligned.m16n8k8.row.col.f32.tf32.tf32.f32 "
        "{%0,%1,%2,%3}, {%4,%5,%6,%7}, {%8,%9}, {%0,%1,%2,%3};"
        : "+f"(c[0]), "+f"(c[1]), "+f"(c[2]), "+f"(c[3])
        : "r"(a[0]), "r"(a[1]), "r"(a[2]), "r"(a[3]), "r"(b[0]), "r"(b[1]));
}

// ---------------- elementwise kernels ----------------
__global__ void zero_kernel(float* comb, int n, int* counts) {
    int i = blockIdx.x * blockDim.x + threadIdx.x;
    if (i < n) comb[i] = 0.f;
    if (i < E) counts[i] = 0;
}

__global__ void posadd_kernel(const float* __restrict__ x, float* __restrict__ h) {
    int t = blockIdx.x;
    int s = t & 1023;
    const float LOG1E4 = 9.210340371976184f;
    for (int d = threadIdx.x; d < D; d += 256) {
        int j2 = d & ~1;
        float div = expf(-LOG1E4 * (float)j2 * (1.0f / (float)D));
        float a = (float)s * div;
        float pe = (d & 1) ? cosf(a) : sinf(a);
        h[(size_t)t * D + d] = x[(size_t)t * D + d] + pe;
    }
}

__global__ void ln_dual_kernel(const float* __restrict__ hbuf,
                               const float* __restrict__ g, const float* __restrict__ b,
                               float* __restrict__ xhat, float* __restrict__ r) {
    __shared__ float sh[256];
    int t = blockIdx.x, tid = threadIdx.x;
    const float* row = hbuf + (size_t)t * D;
    float v[4];
    float s = 0.f;
#pragma unroll
    for (int i = 0; i < 4; i++) { v[i] = row[tid + 256 * i]; s += v[i]; }
    s = block_reduce_sum256(s, sh);
    float mean = s * (1.f / (float)D);
    float q = 0.f;
#pragma unroll
    for (int i = 0; i < 4; i++) { float dd = v[i] - mean; q += dd * dd; }
    q = block_reduce_sum256(q, sh);
    float rstd = rsqrtf(q * (1.f / (float)D) + LN_EPS);
#pragma unroll
    for (int i = 0; i < 4; i++) {
        int d = tid + 256 * i;
        float xh = (v[i] - mean) * rstd;
        xhat[(size_t)t * D + d] = xh;
        r[(size_t)t * D + d] = to_tf32(xh * g[d] + b[d]);
    }
}

template <bool ROUND>
__global__ void ln_affine_kernel(const float* __restrict__ X, const float* __restrict__ X2,
                                 const float* __restrict__ g, const float* __restrict__ b,
                                 float* __restrict__ out) {
    __shared__ float sh[256];
    int t = blockIdx.x, tid = threadIdx.x;
    float v[4];
    float s = 0.f;
#pragma unroll
    for (int i = 0; i < 4; i++) {
        int d = tid + 256 * i;
        float val = X[(size_t)t * D + d];
        if (X2) val += X2[(size_t)t * D + d];
        v[i] = val; s += val;
    }
    s = block_reduce_sum256(s, sh);
    float mean = s * (1.f / (float)D);
    float q = 0.f;
#pragma unroll
    for (int i = 0; i < 4; i++) { float dd = v[i] - mean; q += dd * dd; }
    q = block_reduce_sum256(q, sh);
    float rstd = rsqrtf(q * (1.f / (float)D) + LN_EPS);
#pragma unroll
    for (int i = 0; i < 4; i++) {
        int d = tid + 256 * i;
        float o = (v[i] - mean) * rstd * g[d] + b[d];
        out[(size_t)t * D + d] = ROUND ? to_tf32(o) : o;
    }
}

// ---------------- tf32 mma.sync GEMM ----------------
// C[M,N] = act(A[M,K] @ B[K,N] + bias[N]); A [M][K] K-contig, B [K][N] N-contig.
// BM=BN=128, BK=16, 256 threads (8 warps, 2x4), 3-stage cp.async pipeline.
// smem per stage: A 128x16 @stride20 (2560 f), B 16x128 @stride136 (2176 f).
#define AST   20
#define BST   136
#define STG_F 4736          // floats per stage
#define STG_B (STG_F * 4)   // bytes per stage
#define NSTG  3
#define SMEM_BYTES (NSTG * STG_B)

template <bool DOGELU, bool ROUND, bool GROUPED>
__global__ void __launch_bounds__(256, 2)
mma_gemm(const float* __restrict__ Abase, const float* __restrict__ Ball,
         const float* __restrict__ biasall, float* __restrict__ Cbase,
         const int* __restrict__ counts, const int* __restrict__ bases,
         int M_in, int N, int K) {
    int e = GROUPED ? blockIdx.z : 0;
    int M = GROUPED ? counts[e] : M_in;
    int m0 = blockIdx.y * 128;
    if (m0 >= M) return;
    int n0 = blockIdx.x * 128;
    const float* A = GROUPED ? Abase + (size_t)bases[e] * K : Abase;
    const float* B = GROUPED ? Ball + (size_t)e * (size_t)K * N : Ball;
    const float* bias = GROUPED ? biasall + (size_t)e * N : biasall;
    float* C = GROUPED ? Cbase + (size_t)bases[e] * N : Cbase;

    extern __shared__ float smf[];
    uint32_t sbase = smem_u32(smf);
    int tid = threadIdx.x;
    int wid = tid >> 5, lane = tid & 31;
    int gq = lane >> 2, qq = lane & 3;      // group / thread-in-group
    int m0w = (wid & 1) * 64;               // warp m offset
    int n0w = (wid >> 1) * 32;              // warp n offset

    // cp.async source/dst precompute
    int ar = tid >> 2, aq = tid & 3;        // A: rows ar, ar+64; quad aq
    int br = tid >> 5, bq = tid & 31;       // B: rows br, br+8; quad bq
    uint32_t adst0 = ar * 80 + aq * 16;
    uint32_t adst1 = adst0 + 64 * 80;
    uint32_t bdst0 = 10240 + br * 544 + bq * 16;
    uint32_t bdst1 = bdst0 + 8 * 544;
    int arow0 = m0 + ar, arow1 = m0 + ar + 64;
    uint32_t asz0 = (arow0 < M) ? 16u : 0u;
    uint32_t asz1 = (arow1 < M) ? 16u : 0u;
    const float* asrc0 = A + (size_t)((arow0 < M) ? arow0 : 0) * K + aq * 4;
    const float* asrc1 = A + (size_t)((arow1 < M) ? arow1 : 0) * K + aq * 4;
    const float* bsrc0 = B + (size_t)br * N + n0 + bq * 4;
    const float* bsrc1 = bsrc0 + (size_t)8 * N;

    const int NC = K / 16;

    float acc[4][4][4];
#pragma unroll
    for (int i = 0; i < 4; i++)
#pragma unroll
        for (int j = 0; j < 4; j++)
#pragma unroll
            for (int l = 0; l < 4; l++) acc[i][j][l] = 0.f;

    // prologue: stages 0,1
#pragma unroll
    for (int pk = 0; pk < 2; pk++) {
        uint32_t sb = sbase + pk * STG_B;
        int k0 = pk * 16;
        CP_ASYNC_CG(sb + adst0, asrc0 + k0, asz0);
        CP_ASYNC_CG(sb + adst1, asrc1 + k0, asz1);
        CP_ASYNC_CG(sb + bdst0, bsrc0 + (size_t)k0 * N, 16u);
        CP_ASYNC_CG(sb + bdst1, bsrc1 + (size_t)k0 * N, 16u);
        CP_COMMIT();
    }

    for (int kc = 0; kc < NC; kc++) {
        CP_WAIT1();
        __syncthreads();
        if (kc + 2 < NC) {
            int s = (kc + 2) % NSTG;
            uint32_t sb = sbase + s * STG_B;
            int k0 = (kc + 2) * 16;
            CP_ASYNC_CG(sb + adst0, asrc0 + k0, asz0);
            CP_ASYNC_CG(sb + adst1, asrc1 + k0, asz1);
            CP_ASYNC_CG(sb + bdst0, bsrc0 + (size_t)k0 * N, 16u);
            CP_ASYNC_CG(sb + bdst1, bsrc1 + (size_t)k0 * N, 16u);
            CP_COMMIT();
        }
        const float* As = smf + (kc % NSTG) * STG_F;
        const float* Bs = As + 2560;
#pragma unroll
        for (int k8 = 0; k8 < 2; k8++) {
            int kk = k8 * 8;
            uint32_t a[4][4], b[4][2];
#pragma unroll
            for (int mt = 0; mt < 4; mt++) {
                int r = m0w + mt * 16 + gq;
                a[mt][0] = __float_as_uint(As[r * AST + kk + qq]);
                a[mt][1] = __float_as_uint(As[(r + 8) * AST + kk + qq]);
                a[mt][2] = __float_as_uint(As[r * AST + kk + qq + 4]);
                a[mt][3] = __float_as_uint(As[(r + 8) * AST + kk + qq + 4]);
            }
#pragma unroll
            for (int nt = 0; nt < 4; nt++) {
                int c = n0w + nt * 8 + gq;
                b[nt][0] = __float_as_uint(Bs[(kk + qq) * BST + c]);
                b[nt][1] = __float_as_uint(Bs[(kk + qq + 4) * BST + c]);
            }
#pragma unroll
            for (int mt = 0; mt < 4; mt++)
#pragma unroll
                for (int nt = 0; nt < 4; nt++)
                    mma_tf32(acc[mt][nt], a[mt], b[nt]);
        }
        __syncthreads();
    }

    // epilogue: bias + activation + store (float2 per c-pair)
#pragma unroll
    for (int mt = 0; mt < 4; mt++) {
        int row0 = m0 + m0w + mt * 16 + gq;
        int row1 = row0 + 8;
#pragma unroll
        for (int nt = 0; nt < 4; nt++) {
            int col = n0 + n0w + nt * 8 + 2 * qq;
            float b0 = bias[col], b1 = bias[col + 1];
            float v0 = acc[mt][nt][0] + b0;
            float v1 = acc[mt][nt][1] + b1;
            float v2 = acc[mt][nt][2] + b0;
            float v3 = acc[mt][nt][3] + b1;
            if (DOGELU) { v0 = gelu_f(v0); v1 = gelu_f(v1); v2 = gelu_f(v2); v3 = gelu_f(v3); }
            if (ROUND)  { v0 = to_tf32(v0); v1 = to_tf32(v1); v2 = to_tf32(v2); v3 = to_tf32(v3); }
            if (row0 < M) *(float2*)(C + (size_t)row0 * N + col) = make_float2(v0, v1);
            if (row1 < M) *(float2*)(C + (size_t)row1 * N + col) = make_float2(v2, v3);
        }
    }
}

// ---------------- router / gather / scatter ----------------
__global__ void router_kernel(const float* __restrict__ rh, const float* __restrict__ w2,
                              const float* __restrict__ b2, const float* __restrict__ temp,
                              int* __restrict__ counts, int* __restrict__ perm,
                              float* __restrict__ gatew) {
    __shared__ float sh[E * 256];
    int t = blockIdx.x, tid = threadIdx.x;
    float acc[E];
#pragma unroll
    for (int e = 0; e < E; e++) acc[e] = 0.f;
    const float* row = rh + (size_t)t * H;
    for (int k = tid; k < H; k += 256) {
        float v = row[k];
        const float4* w = (const float4*)(w2 + (size_t)k * E);
        float4 w0 = w[0], w1 = w[1];
        acc[0] += v * w0.x; acc[1] += v * w0.y; acc[2] += v * w0.z; acc[3] += v * w0.w;
        acc[4] += v * w1.x; acc[5] += v * w1.y; acc[6] += v * w1.z; acc[7] += v * w1.w;
    }
#pragma unroll
    for (int e = 0; e < E; e++) sh[e * 256 + tid] = acc[e];
    __syncthreads();
#pragma unroll
    for (int s = 128; s > 0; s >>= 1) {
        if (tid < s)
#pragma unroll
            for (int e = 0; e < E; e++) sh[e * 256 + tid] += sh[e * 256 + tid + s];
        __syncthreads();
    }
    if (tid == 0) {
        float invt = 1.0f / temp[0];
        float l[E], p[E];
        float mx = -1e30f;
#pragma unroll
        for (int e = 0; e < E; e++) { l[e] = (sh[e * 256] + b2[e]) * invt; mx = fmaxf(mx, l[e]); }
        float se = 0.f;
#pragma unroll
        for (int e = 0; e < E; e++) { p[e] = expf(l[e] - mx); se += p[e]; }
        float inv = 1.0f / se;
#pragma unroll
        for (int e = 0; e < E; e++) p[e] *= inv;
        int i1 = 0;
#pragma unroll
        for (int e = 1; e < E; e++) if (p[e] > p[i1]) i1 = e;
        int i2 = (i1 == 0) ? 1 : 0;
#pragma unroll
        for (int e = 0; e < E; e++) if (e != i1 && p[e] > p[i2]) i2 = e;
        int pos1 = atomicAdd(&counts[i1], 1);
        perm[i1 * NTOK + pos1] = t;
        gatew[i1 * NTOK + pos1] = p[i1];
        int pos2 = atomicAdd(&counts[i2], 1);
        perm[i2 * NTOK + pos2] = t;
        gatew[i2 * NTOK + pos2] = p[i2];
    }
}

__global__ void base_kernel(const int* __restrict__ counts, int* __restrict__ bases) {
    int s = 0;
    for (int e = 0; e < E; e++) { bases[e] = s; s += counts[e]; }
}

__global__ void gather_kernel(const float* __restrict__ xhat, const float* __restrict__ elng,
                              const float* __restrict__ elnb, const int* __restrict__ counts,
                              const int* __restrict__ bases, const int* __restrict__ perm,
                              float* __restrict__ y) {
    int e = blockIdx.y, i = blockIdx.x;
    if (i >= counts[e]) return;
    int t = perm[e * NTOK + i];
    const float* src = xhat + (size_t)t * D;
    const float* g = elng + (size_t)e * D;
    const float* b = elnb + (size_t)e * D;
    float* dst = y + (size_t)(bases[e] + i) * D;
    for (int d = threadIdx.x; d < D; d += 256)
        dst[d] = to_tf32(src[d] * g[d] + b[d]);
}

__global__ void scatter_kernel(const float* __restrict__ f2, const int* __restrict__ counts,
                               const int* __restrict__ bases, const int* __restrict__ perm,
                               const float* __restrict__ gatew, float* __restrict__ comb) {
    int e = blockIdx.y, i = blockIdx.x;
    if (i >= counts[e]) return;
    int t = perm[e * NTOK + i];
    float gw = gatew[e * NTOK + i];
    const float* src = f2 + (size_t)(bases[e] + i) * D;
    float* dst = comb + (size_t)t * D;
    for (int d = threadIdx.x; d < D; d += 256)
        atomicAdd(&dst[d], gw * src[d]);
}

// ---------------- launch ----------------
extern "C" void kernel_launch(void* const* d_in, const int* in_sizes, int n_in,
                              void* d_out, int out_size) {
    const float* x      = (const float*)d_in[0];
    const float* r_ln_g = (const float*)d_in[1];
    const float* r_ln_b = (const float*)d_in[2];
    const float* r_w1   = (const float*)d_in[3];
    const float* r_b1   = (const float*)d_in[4];
    const float* r_w2   = (const float*)d_in[5];
    const float* r_b2   = (const float*)d_in[6];
    const float* temp   = (const float*)d_in[7];
    const float* e_ln_g = (const float*)d_in[8];
    const float* e_ln_b = (const float*)d_in[9];
    const float* e_w1   = (const float*)d_in[10];
    const float* e_b1   = (const float*)d_in[11];
    const float* e_w2   = (const float*)d_in[12];
    const float* e_b2   = (const float*)d_in[13];
    const float* c_ln_g = (const float*)d_in[14];
    const float* c_ln_b = (const float*)d_in[15];
    const float* c_w1   = (const float*)d_in[16];
    const float* c_b1   = (const float*)d_in[17];
    const float* c_w2   = (const float*)d_in[18];
    const float* c_b2   = (const float*)d_in[19];
    const float* o_ln_g = (const float*)d_in[20];
    const float* o_ln_b = (const float*)d_in[21];
    float* out = (float*)d_out;

    float *p_h, *p_xhat, *p_r, *p_rh, *p_gatew, *p_y, *p_f1, *p_f2, *p_comb, *p_cln, *p_ch, *p_co;
    int *p_counts, *p_base, *p_perm;
    cudaGetSymbolAddress((void**)&p_h, g_h);
    cudaGetSymbolAddress((void**)&p_xhat, g_xhat);
    cudaGetSymbolAddress((void**)&p_r, g_r);
    cudaGetSymbolAddress((void**)&p_rh, g_rh);
    cudaGetSymbolAddress((void**)&p_counts, g_counts);
    cudaGetSymbolAddress((void**)&p_base, g_base);
    cudaGetSymbolAddress((void**)&p_perm, g_perm);
    cudaGetSymbolAddress((void**)&p_gatew, g_gatew);
    cudaGetSymbolAddress((void**)&p_y, g_y);
    cudaGetSymbolAddress((void**)&p_f1, g_f1);
    cudaGetSymbolAddress((void**)&p_f2, g_f2);
    cudaGetSymbolAddress((void**)&p_comb, g_comb);
    cudaGetSymbolAddress((void**)&p_cln, g_cln);
    cudaGetSymbolAddress((void**)&p_ch, g_ch);
    cudaGetSymbolAddress((void**)&p_co, g_co);

    cudaFuncSetAttribute(mma_gemm<true,  false, false>, cudaFuncAttributeMaxDynamicSharedMemorySize, SMEM_BYTES);
    cudaFuncSetAttribute(mma_gemm<true,  true,  true >, cudaFuncAttributeMaxDynamicSharedMemorySize, SMEM_BYTES);
    cudaFuncSetAttribute(mma_gemm<false, false, true >, cudaFuncAttributeMaxDynamicSharedMemorySize, SMEM_BYTES);
    cudaFuncSetAttribute(mma_gemm<true,  true,  false>, cudaFuncAttributeMaxDynamicSharedMemorySize, SMEM_BYTES);
    cudaFuncSetAttribute(mma_gemm<false, false, false>, cudaFuncAttributeMaxDynamicSharedMemorySize, SMEM_BYTES);

    // 0. zero combined + counts
    zero_kernel<<<(NTOK * D + 255) / 256, 256>>>(p_comb, NTOK * D, p_counts);
    // 1. h = x + pos
    posadd_kernel<<<NTOK, 256>>>(x, p_h);
    // 2. shared LN stats -> xhat, router input r (tf32-rounded)
    ln_dual_kernel<<<NTOK, 256>>>(p_h, r_ln_g, r_ln_b, p_xhat, p_r);
    // 3. router hidden: rh = gelu(r @ r_w1 + r_b1)
    mma_gemm<true, false, false><<<dim3(H / 128, NTOK / 128), 256, SMEM_BYTES>>>(
        p_r, r_w1, r_b1, p_rh, nullptr, nullptr, NTOK, H, D);
    // 4. router logits -> top2 -> compaction
    router_kernel<<<NTOK, 256>>>(p_rh, r_w2, r_b2, temp, p_counts, p_perm, p_gatew);
    // 5. prefix sums
    base_kernel<<<1, 1>>>(p_counts, p_base);
    // 6. gather expert inputs (per-expert LN affine, tf32-rounded)
    gather_kernel<<<dim3(NTOK, E), 256>>>(p_xhat, e_ln_g, e_ln_b, p_counts, p_base, p_perm, p_y);
    // 7. expert FFN layer 1
    mma_gemm<true, true, true><<<dim3(HE / 128, NTOK / 128, E), 256, SMEM_BYTES>>>(
        p_y, e_w1, e_b1, p_f1, p_counts, p_base, 0, HE, D);
    // 8. expert FFN layer 2
    mma_gemm<false, false, true><<<dim3(D / 128, NTOK / 128, E), 256, SMEM_BYTES>>>(
        p_f1, e_w2, e_b2, p_f2, p_counts, p_base, 0, D, HE);
    // 9. scatter-combine with gates
    scatter_kernel<<<dim3(NTOK, E), 256>>>(p_f2, p_counts, p_base, p_perm, p_gatew, p_comb);
    // 10. combiner LN (tf32 out)
    ln_affine_kernel<true><<<NTOK, 256>>>(p_comb, nullptr, c_ln_g, c_ln_b, p_cln);
    // 11. combiner MLP
    mma_gemm<true, true, false><<<dim3(2 * D / 128, NTOK / 128), 256, SMEM_BYTES>>>(
        p_cln, c_w1, c_b1, p_ch, nullptr, nullptr, NTOK, 2 * D, D);
    mma_gemm<false, false, false><<<dim3(D / 128, NTOK / 128), 256, SMEM_BYTES>>>(
        p_ch, c_w2, c_b2, p_co, nullptr, nullptr, NTOK, D, 2 * D);
    // 12. out = LN(h + co)
    ln_affine_kernel<false><<<NTOK, 256>>>(p_h, p_co, o_ln_g, o_ln_b, out);
}

// round 4
// speedup vs baseline: 3.4287x; 1.0704x over previous
#include <cuda_runtime.h>
#include <cstdint>
#include <math.h>

// ---------------- problem constants ----------------
#define NTOK 2048      // B*S
#define D    1024
#define H    4096
#define HE   4096
#define E    8
#define LN_EPS 1e-5f

// ---------------- scratch (device globals) ----------------
__device__ float g_h    [NTOK * D];
__device__ float g_xhat [NTOK * D];
__device__ float g_r    [NTOK * D];
__device__ float g_rh   [NTOK * H];
__device__ int   g_counts[E];
__device__ int   g_base  [E];
__device__ int   g_perm  [E * NTOK];
__device__ int   g_te   [NTOK * 2];      // per-token expert ids
__device__ int   g_tp   [NTOK * 2];      // per-token slot within expert
__device__ float g_tg   [NTOK * 2];      // per-token gates
__device__ float g_y    [2 * NTOK * D];
__device__ float g_f1   [2 * NTOK * HE];
__device__ float g_f2   [2 * NTOK * D];
__device__ float g_cln  [NTOK * D];
__device__ float g_ch   [NTOK * 2 * D];
__device__ float g_co   [NTOK * D];

// ---------------- helpers ----------------
__device__ __forceinline__ float gelu_f(float x) {
    return 0.5f * x * (1.0f + erff(x * 0.7071067811865475f));
}
__device__ __forceinline__ float to_tf32(float x) {
    uint32_t u;
    asm("cvt.rna.tf32.f32 %0, %1;" : "=r"(u) : "f"(x));
    return __uint_as_float(u);
}
__device__ __forceinline__ uint32_t smem_u32(const void* p) {
    uint32_t a;
    asm("{ .reg .u64 t; cvta.to.shared.u64 t, %1; cvt.u32.u64 %0, t; }" : "=r"(a) : "l"(p));
    return a;
}
__device__ __forceinline__ float block_reduce_sum256(float v, float* sh) {
    int tid = threadIdx.x;
    sh[tid] = v;
    __syncthreads();
#pragma unroll
    for (int s = 128; s > 0; s >>= 1) {
        if (tid < s) sh[tid] += sh[tid + s];
        __syncthreads();
    }
    float r = sh[0];
    __syncthreads();
    return r;
}

// cp.async (baseline PTX, compute_80+)
#define CP_ASYNC_CG(dst, src, srcsz) \
    asm volatile("cp.async.cg.shared.global [%0], [%1], 16, %2;" \
        :: "r"(dst), "l"(src), "r"(srcsz) : "memory")
#define CP_COMMIT() asm volatile("cp.async.commit_group;" ::: "memory")
#define CP_WAIT2()  asm volatile("cp.async.wait_group 2;" ::: "memory")

__device__ __forceinline__ void mma_tf32(float* c, const uint32_t* a, const uint32_t* b) {
    asm volatile(
        "mma.sync.aligned.m16n8k8.row.col.f32.tf32.tf32.f32 "
        "{%0,%1,%2,%3}, {%4,%5,%6,%7}, {%8,%9}, {%0,%1,%2,%3};"
        : "+f"(c[0]), "+f"(c[1]), "+f"(c[2]), "+f"(c[3])
        : "r"(a[0]), "r"(a[1]), "r"(a[2]), "r"(a[3]), "r"(b[0]), "r"(b[1]));
}

// ---------------- fused elementwise kernels ----------------
__global__ void zero_counts_kernel(int* counts) {
    if (threadIdx.x < E) counts[threadIdx.x] = 0;
}

// h = x + pos; LN(h) -> xhat (no affine), r = tf32(xhat*g+b)
__global__ void posln_kernel(const float* __restrict__ x,
                             const float* __restrict__ g, const float* __restrict__ b,
                             float* __restrict__ h, float* __restrict__ xhat,
                             float* __restrict__ r) {
    __shared__ float sh[256];
    int t = blockIdx.x, tid = threadIdx.x;
    int sp = t & 1023;
    const float LOG1E4 = 9.210340371976184f;
    float v[4];
    float s = 0.f;
#pragma unroll
    for (int i = 0; i < 4; i++) {
        int d = tid + 256 * i;
        int j2 = d & ~1;
        float div = expf(-LOG1E4 * (float)j2 * (1.0f / (float)D));
        float a = (float)sp * div;
        float pe = (d & 1) ? cosf(a) : sinf(a);
        float val = x[(size_t)t * D + d] + pe;
        v[i] = val; s += val;
        h[(size_t)t * D + d] = val;
    }
    s = block_reduce_sum256(s, sh);
    float mean = s * (1.f / (float)D);
    float q = 0.f;
#pragma unroll
    for (int i = 0; i < 4; i++) { float dd = v[i] - mean; q += dd * dd; }
    q = block_reduce_sum256(q, sh);
    float rstd = rsqrtf(q * (1.f / (float)D) + LN_EPS);
#pragma unroll
    for (int i = 0; i < 4; i++) {
        int d = tid + 256 * i;
        float xh = (v[i] - mean) * rstd;
        xhat[(size_t)t * D + d] = xh;
        r[(size_t)t * D + d] = to_tf32(xh * g[d] + b[d]);
    }
}

template <bool ROUND>
__global__ void ln_affine_kernel(const float* __restrict__ X, const float* __restrict__ X2,
                                 const float* __restrict__ g, const float* __restrict__ b,
                                 float* __restrict__ out) {
    __shared__ float sh[256];
    int t = blockIdx.x, tid = threadIdx.x;
    float v[4];
    float s = 0.f;
#pragma unroll
    for (int i = 0; i < 4; i++) {
        int d = tid + 256 * i;
        float val = X[(size_t)t * D + d];
        if (X2) val += X2[(size_t)t * D + d];
        v[i] = val; s += val;
    }
    s = block_reduce_sum256(s, sh);
    float mean = s * (1.f / (float)D);
    float q = 0.f;
#pragma unroll
    for (int i = 0; i < 4; i++) { float dd = v[i] - mean; q += dd * dd; }
    q = block_reduce_sum256(q, sh);
    float rstd = rsqrtf(q * (1.f / (float)D) + LN_EPS);
#pragma unroll
    for (int i = 0; i < 4; i++) {
        int d = tid + 256 * i;
        float o = (v[i] - mean) * rstd * g[d] + b[d];
        out[(size_t)t * D + d] = ROUND ? to_tf32(o) : o;
    }
}

// combined = g1*f2[row1] + g2*f2[row2]; cln = tf32(LN(combined)*g+b)
__global__ void combine_ln_kernel(const float* __restrict__ f2, const int* __restrict__ bases,
                                  const int* __restrict__ te, const int* __restrict__ tp,
                                  const float* __restrict__ tg,
                                  const float* __restrict__ g, const float* __restrict__ b,
                                  float* __restrict__ cln) {
    __shared__ float sh[256];
    int t = blockIdx.x, tid = threadIdx.x;
    int e1 = te[2 * t], e2 = te[2 * t + 1];
    int p1 = tp[2 * t], p2 = tp[2 * t + 1];
    float g1 = tg[2 * t], g2 = tg[2 * t + 1];
    const float* r1 = f2 + (size_t)(bases[e1] + p1) * D;
    const float* r2 = f2 + (size_t)(bases[e2] + p2) * D;
    float v[4];
    float s = 0.f;
#pragma unroll
    for (int i = 0; i < 4; i++) {
        int d = tid + 256 * i;
        float val = g1 * r1[d] + g2 * r2[d];
        v[i] = val; s += val;
    }
    s = block_reduce_sum256(s, sh);
    float mean = s * (1.f / (float)D);
    float q = 0.f;
#pragma unroll
    for (int i = 0; i < 4; i++) { float dd = v[i] - mean; q += dd * dd; }
    q = block_reduce_sum256(q, sh);
    float rstd = rsqrtf(q * (1.f / (float)D) + LN_EPS);
#pragma unroll
    for (int i = 0; i < 4; i++) {
        int d = tid + 256 * i;
        cln[(size_t)t * D + d] = to_tf32((v[i] - mean) * rstd * g[d] + b[d]);
    }
}

// ---------------- tf32 mma.sync GEMM (warp tile 64x64) ----------------
// C[M,N] = act(A[M,K] @ B[K,N] + bias[N]); A [M][K] K-contig, B [K][N] N-contig.
// BM=BN=128, BK=16, 128 threads (4 warps 2x2, each 64x64), 4-stage cp.async.
// smem/stage: A 128x16 @stride20 (2560 f), B 16x128 @stride136 (2176 f).
#define AST   20
#define BST   136
#define STG_F 4736          // floats per stage
#define STG_B (STG_F * 4)   // bytes per stage
#define NSTG  4
#define SMEM_BYTES (NSTG * STG_B)

template <bool DOGELU, bool ROUND, bool GROUPED>
__global__ void __launch_bounds__(128, 2)
mma_gemm(const float* __restrict__ Abase, const float* __restrict__ Ball,
         const float* __restrict__ biasall, float* __restrict__ Cbase,
         const int* __restrict__ counts, const int* __restrict__ bases,
         int M_in, int N, int K) {
    int e = GROUPED ? blockIdx.z : 0;
    int M = GROUPED ? counts[e] : M_in;
    int m0 = blockIdx.y * 128;
    if (m0 >= M) return;
    int n0 = blockIdx.x * 128;
    const float* A = GROUPED ? Abase + (size_t)bases[e] * K : Abase;
    const float* B = GROUPED ? Ball + (size_t)e * (size_t)K * N : Ball;
    const float* bias = GROUPED ? biasall + (size_t)e * N : biasall;
    float* C = GROUPED ? Cbase + (size_t)bases[e] * N : Cbase;

    extern __shared__ float smf[];
    uint32_t sbase = smem_u32(smf);
    int tid = threadIdx.x;
    int wid = tid >> 5, lane = tid & 31;
    int gq = lane >> 2, qq = lane & 3;
    int m0w = (wid & 1) * 64;
    int n0w = (wid >> 1) * 64;

    // cp.async: A 4 rows/thread (32-apart), B 4 rows/thread (4-apart)
    int aq = tid & 3, ar = tid >> 2;        // ar 0..31
    int bq = tid & 31, br = tid >> 5;       // br 0..3
    uint32_t adst[4], bdst[4];
    const float* asrc[4];
    const float* bsrc[4];
    uint32_t asz[4];
#pragma unroll
    for (int i = 0; i < 4; i++) {
        int r = ar + 32 * i;
        adst[i] = (uint32_t)(r * 80 + aq * 16);
        int row = m0 + r;
        asz[i] = (row < M) ? 16u : 0u;
        asrc[i] = A + (size_t)((row < M) ? row : 0) * K + aq * 4;
        int rb = br + 4 * i;
        bdst[i] = (uint32_t)(10240 + rb * 544 + bq * 16);
        bsrc[i] = B + (size_t)rb * N + n0 + bq * 4;
    }

    const int NC = K / 16;

    float acc[4][8][4];
#pragma unroll
    for (int i = 0; i < 4; i++)
#pragma unroll
        for (int j = 0; j < 8; j++)
#pragma unroll
            for (int l = 0; l < 4; l++) acc[i][j][l] = 0.f;

    // prologue: stages 0,1,2
#pragma unroll
    for (int pk = 0; pk < 3; pk++) {
        uint32_t sb = sbase + pk * STG_B;
        int k0 = pk * 16;
#pragma unroll
        for (int i = 0; i < 4; i++) CP_ASYNC_CG(sb + adst[i], asrc[i] + k0, asz[i]);
#pragma unroll
        for (int i = 0; i < 4; i++) CP_ASYNC_CG(sb + bdst[i], bsrc[i] + (size_t)k0 * N, 16u);
        CP_COMMIT();
    }

    for (int kc = 0; kc < NC; kc++) {
        CP_WAIT2();
        __syncthreads();
        if (kc + 3 < NC) {
            uint32_t sb = sbase + ((kc + 3) & 3) * STG_B;
            int k0 = (kc + 3) * 16;
#pragma unroll
            for (int i = 0; i < 4; i++) CP_ASYNC_CG(sb + adst[i], asrc[i] + k0, asz[i]);
#pragma unroll
            for (int i = 0; i < 4; i++) CP_ASYNC_CG(sb + bdst[i], bsrc[i] + (size_t)k0 * N, 16u);
        }
        CP_COMMIT();
        const float* As = smf + (kc & 3) * STG_F;
        const float* Bs = As + 2560;
#pragma unroll
        for (int k8 = 0; k8 < 2; k8++) {
            int kk = k8 * 8;
            uint32_t a[4][4], b[8][2];
#pragma unroll
            for (int mt = 0; mt < 4; mt++) {
                int r = m0w + mt * 16 + gq;
                a[mt][0] = __float_as_uint(As[r * AST + kk + qq]);
                a[mt][1] = __float_as_uint(As[(r + 8) * AST + kk + qq]);
                a[mt][2] = __float_as_uint(As[r * AST + kk + qq + 4]);
                a[mt][3] = __float_as_uint(As[(r + 8) * AST + kk + qq + 4]);
            }
#pragma unroll
            for (int nt = 0; nt < 8; nt++) {
                int c = n0w + nt * 8 + gq;
                b[nt][0] = __float_as_uint(Bs[(kk + qq) * BST + c]);
                b[nt][1] = __float_as_uint(Bs[(kk + qq + 4) * BST + c]);
            }
#pragma unroll
            for (int mt = 0; mt < 4; mt++)
#pragma unroll
                for (int nt = 0; nt < 8; nt++)
                    mma_tf32(acc[mt][nt], a[mt], b[nt]);
        }
    }

    // epilogue
#pragma unroll
    for (int mt = 0; mt < 4; mt++) {
        int row0 = m0 + m0w + mt * 16 + gq;
        int row1 = row0 + 8;
#pragma unroll
        for (int nt = 0; nt < 8; nt++) {
            int col = n0 + n0w + nt * 8 + 2 * qq;
            float b0 = bias[col], b1 = bias[col + 1];
            float v0 = acc[mt][nt][0] + b0;
            float v1 = acc[mt][nt][1] + b1;
            float v2 = acc[mt][nt][2] + b0;
            float v3 = acc[mt][nt][3] + b1;
            if (DOGELU) { v0 = gelu_f(v0); v1 = gelu_f(v1); v2 = gelu_f(v2); v3 = gelu_f(v3); }
            if (ROUND)  { v0 = to_tf32(v0); v1 = to_tf32(v1); v2 = to_tf32(v2); v3 = to_tf32(v3); }
            if (row0 < M) *(float2*)(C + (size_t)row0 * N + col) = make_float2(v0, v1);
            if (row1 < M) *(float2*)(C + (size_t)row1 * N + col) = make_float2(v2, v3);
        }
    }
}

// ---------------- router / gather ----------------
__global__ void router_kernel(const float* __restrict__ rh, const float* __restrict__ w2,
                              const float* __restrict__ b2, const float* __restrict__ temp,
                              int* __restrict__ counts, int* __restrict__ perm,
                              int* __restrict__ te, int* __restrict__ tp,
                              float* __restrict__ tg) {
    __shared__ float sh[E * 256];
    int t = blockIdx.x, tid = threadIdx.x;
    float acc[E];
#pragma unroll
    for (int e = 0; e < E; e++) acc[e] = 0.f;
    const float* row = rh + (size_t)t * H;
    for (int k = tid; k < H; k += 256) {
        float v = row[k];
        const float4* w = (const float4*)(w2 + (size_t)k * E);
        float4 w0 = w[0], w1 = w[1];
        acc[0] += v * w0.x; acc[1] += v * w0.y; acc[2] += v * w0.z; acc[3] += v * w0.w;
        acc[4] += v * w1.x; acc[5] += v * w1.y; acc[6] += v * w1.z; acc[7] += v * w1.w;
    }
#pragma unroll
    for (int e = 0; e < E; e++) sh[e * 256 + tid] = acc[e];
    __syncthreads();
#pragma unroll
    for (int s = 128; s > 0; s >>= 1) {
        if (tid < s)
#pragma unroll
            for (int e = 0; e < E; e++) sh[e * 256 + tid] += sh[e * 256 + tid + s];
        __syncthreads();
    }
    if (tid == 0) {
        float invt = 1.0f / temp[0];
        float l[E], p[E];
        float mx = -1e30f;
#pragma unroll
        for (int e = 0; e < E; e++) { l[e] = (sh[e * 256] + b2[e]) * invt; mx = fmaxf(mx, l[e]); }
        float se = 0.f;
#pragma unroll
        for (int e = 0; e < E; e++) { p[e] = expf(l[e] - mx); se += p[e]; }
        float inv = 1.0f / se;
#pragma unroll
        for (int e = 0; e < E; e++) p[e] *= inv;
        int i1 = 0;
#pragma unroll
        for (int e = 1; e < E; e++) if (p[e] > p[i1]) i1 = e;
        int i2 = (i1 == 0) ? 1 : 0;
#pragma unroll
        for (int e = 0; e < E; e++) if (e != i1 && p[e] > p[i2]) i2 = e;
        int pos1 = atomicAdd(&counts[i1], 1);
        perm[i1 * NTOK + pos1] = t;
        int pos2 = atomicAdd(&counts[i2], 1);
        perm[i2 * NTOK + pos2] = t;
        te[2 * t] = i1; tp[2 * t] = pos1; tg[2 * t] = p[i1];
        te[2 * t + 1] = i2; tp[2 * t + 1] = pos2; tg[2 * t + 1] = p[i2];
    }
}

__global__ void base_kernel(const int* __restrict__ counts, int* __restrict__ bases) {
    int s = 0;
    for (int e = 0; e < E; e++) { bases[e] = s; s += counts[e]; }
}

__global__ void gather_kernel(const float* __restrict__ xhat, const float* __restrict__ elng,
                              const float* __restrict__ elnb, const int* __restrict__ counts,
                              const int* __restrict__ bases, const int* __restrict__ perm,
                              float* __restrict__ y) {
    int e = blockIdx.y, i = blockIdx.x;
    if (i >= counts[e]) return;
    int t = perm[e * NTOK + i];
    const float* src = xhat + (size_t)t * D;
    const float* g = elng + (size_t)e * D;
    const float* b = elnb + (size_t)e * D;
    float* dst = y + (size_t)(bases[e] + i) * D;
    for (int d = threadIdx.x; d < D; d += 256)
        dst[d] = to_tf32(src[d] * g[d] + b[d]);
}

// ---------------- launch ----------------
extern "C" void kernel_launch(void* const* d_in, const int* in_sizes, int n_in,
                              void* d_out, int out_size) {
    const float* x      = (const float*)d_in[0];
    const float* r_ln_g = (const float*)d_in[1];
    const float* r_ln_b = (const float*)d_in[2];
    const float* r_w1   = (const float*)d_in[3];
    const float* r_b1   = (const float*)d_in[4];
    const float* r_w2   = (const float*)d_in[5];
    const float* r_b2   = (const float*)d_in[6];
    const float* temp   = (const float*)d_in[7];
    const float* e_ln_g = (const float*)d_in[8];
    const float* e_ln_b = (const float*)d_in[9];
    const float* e_w1   = (const float*)d_in[10];
    const float* e_b1   = (const float*)d_in[11];
    const float* e_w2   = (const float*)d_in[12];
    const float* e_b2   = (const float*)d_in[13];
    const float* c_ln_g = (const float*)d_in[14];
    const float* c_ln_b = (const float*)d_in[15];
    const float* c_w1   = (const float*)d_in[16];
    const float* c_b1   = (const float*)d_in[17];
    const float* c_w2   = (const float*)d_in[18];
    const float* c_b2   = (const float*)d_in[19];
    const float* o_ln_g = (const float*)d_in[20];
    const float* o_ln_b = (const float*)d_in[21];
    float* out = (float*)d_out;

    float *p_h, *p_xhat, *p_r, *p_rh, *p_tg, *p_y, *p_f1, *p_f2, *p_cln, *p_ch, *p_co;
    int *p_counts, *p_base, *p_perm, *p_te, *p_tp;
    cudaGetSymbolAddress((void**)&p_h, g_h);
    cudaGetSymbolAddress((void**)&p_xhat, g_xhat);
    cudaGetSymbolAddress((void**)&p_r, g_r);
    cudaGetSymbolAddress((void**)&p_rh, g_rh);
    cudaGetSymbolAddress((void**)&p_counts, g_counts);
    cudaGetSymbolAddress((void**)&p_base, g_base);
    cudaGetSymbolAddress((void**)&p_perm, g_perm);
    cudaGetSymbolAddress((void**)&p_te, g_te);
    cudaGetSymbolAddress((void**)&p_tp, g_tp);
    cudaGetSymbolAddress((void**)&p_tg, g_tg);
    cudaGetSymbolAddress((void**)&p_y, g_y);
    cudaGetSymbolAddress((void**)&p_f1, g_f1);
    cudaGetSymbolAddress((void**)&p_f2, g_f2);
    cudaGetSymbolAddress((void**)&p_cln, g_cln);
    cudaGetSymbolAddress((void**)&p_ch, g_ch);
    cudaGetSymbolAddress((void**)&p_co, g_co);

    cudaFuncSetAttribute(mma_gemm<true,  false, false>, cudaFuncAttributeMaxDynamicSharedMemorySize, SMEM_BYTES);
    cudaFuncSetAttribute(mma_gemm<true,  true,  true >, cudaFuncAttributeMaxDynamicSharedMemorySize, SMEM_BYTES);
    cudaFuncSetAttribute(mma_gemm<false, false, true >, cudaFuncAttributeMaxDynamicSharedMemorySize, SMEM_BYTES);
    cudaFuncSetAttribute(mma_gemm<true,  true,  false>, cudaFuncAttributeMaxDynamicSharedMemorySize, SMEM_BYTES);
    cudaFuncSetAttribute(mma_gemm<false, false, false>, cudaFuncAttributeMaxDynamicSharedMemorySize, SMEM_BYTES);

    // 0. zero expert counts
    zero_counts_kernel<<<1, 32>>>(p_counts);
    // 1+2. h = x + pos; shared LN stats -> xhat; router input r (tf32)
    posln_kernel<<<NTOK, 256>>>(x, r_ln_g, r_ln_b, p_h, p_xhat, p_r);
    // 3. router hidden: rh = gelu(r @ r_w1 + r_b1)
    mma_gemm<true, false, false><<<dim3(H / 128, NTOK / 128), 128, SMEM_BYTES>>>(
        p_r, r_w1, r_b1, p_rh, nullptr, nullptr, NTOK, H, D);
    // 4. router logits -> top2 -> compaction + per-token records
    router_kernel<<<NTOK, 256>>>(p_rh, r_w2, r_b2, temp, p_counts, p_perm, p_te, p_tp, p_tg);
    // 5. prefix sums
    base_kernel<<<1, 1>>>(p_counts, p_base);
    // 6. gather expert inputs (per-expert LN affine, tf32)
    gather_kernel<<<dim3(NTOK, E), 256>>>(p_xhat, e_ln_g, e_ln_b, p_counts, p_base, p_perm, p_y);
    // 7. expert FFN layer 1
    mma_gemm<true, true, true><<<dim3(HE / 128, NTOK / 128, E), 128, SMEM_BYTES>>>(
        p_y, e_w1, e_b1, p_f1, p_counts, p_base, 0, HE, D);
    // 8. expert FFN layer 2
    mma_gemm<false, false, true><<<dim3(D / 128, NTOK / 128, E), 128, SMEM_BYTES>>>(
        p_f1, e_w2, e_b2, p_f2, p_counts, p_base, 0, D, HE);
    // 9+10. combine (gates) + combiner LN fused
    combine_ln_kernel<<<NTOK, 256>>>(p_f2, p_base, p_te, p_tp, p_tg, c_ln_g, c_ln_b, p_cln);
    // 11. combiner MLP
    mma_gemm<true, true, false><<<dim3(2 * D / 128, NTOK / 128), 128, SMEM_BYTES>>>(
        p_cln, c_w1, c_b1, p_ch, nullptr, nullptr, NTOK, 2 * D, D);
    mma_gemm<false, false, false><<<dim3(D / 128, NTOK / 128), 128, SMEM_BYTES>>>(
        p_ch, c_w2, c_b2, p_co, nullptr, nullptr, NTOK, D, 2 * D);
    // 12. out = LN(h + co)
    ln_affine_kernel<false><<<NTOK, 256>>>(p_h, p_co, o_ln_g, o_ln_b, out);
}